// round 1
// baseline (speedup 1.0000x reference)
#include <cuda_runtime.h>
#include <math.h>

// Problem constants
#define TOK 2048     // B*S tokens
#define DIM 1024     // model dim
#define HID 4096     // SwiGLU hidden
#define NE  8        // routed experts
#define NG  9        // 8 routed groups + 1 shared group (index 8)
#define CAP 2048     // per-group row capacity (worst case: all tokens one expert)

// ---------------- device scratch (static, allocation-free) ----------------
__device__ int   g_counts[NE];
__device__ int   g_rows[NE * CAP];        // token id per (expert, slot)
__device__ int   g_tok_e[TOK * 2];
__device__ int   g_tok_p[TOK * 2];
__device__ float g_tok_w[TOK * 2];
__device__ float g_hidden[(size_t)NG * CAP * HID];  // ~302 MB
__device__ float g_y[(size_t)NG * CAP * DIM];       // ~75 MB

// ---------------- packed f32x2 helpers (2x FFMA throughput on sm_103a) ----
__device__ __forceinline__ unsigned long long bcast2(float a) {
    unsigned long long r;
    asm("mov.b64 %0, {%1, %1};" : "=l"(r) : "f"(a));
    return r;
}
__device__ __forceinline__ void fma2(unsigned long long& d,
                                     unsigned long long a,
                                     unsigned long long b) {
    asm("fma.rn.f32x2 %0, %1, %2, %3;" : "=l"(d) : "l"(a), "l"(b), "l"(d));
}
__device__ __forceinline__ float2 up2(unsigned long long v) {
    float2 f;
    f.x = __int_as_float((unsigned int)(v & 0xffffffffull));
    f.y = __int_as_float((unsigned int)(v >> 32));
    return f;
}

// ---------------- 1) router: logits, top-2, gather lists -------------------
__global__ __launch_bounds__(256) void router_k(const float* __restrict__ x,
                                                const float* __restrict__ rw,
                                                float* __restrict__ logits) {
    int t = blockIdx.x;
    __shared__ float xs[DIM];
    __shared__ float lg[NE];
    int tid = threadIdx.x;
    for (int i = tid; i < DIM; i += 256) xs[i] = x[(size_t)t * DIM + i];
    __syncthreads();

    int w = tid >> 5, lane = tid & 31;  // 8 warps, one expert each
    const float* r = rw + w * DIM;
    float s = 0.f;
    for (int i = lane; i < DIM; i += 32) s += xs[i] * r[i];
    #pragma unroll
    for (int o = 16; o; o >>= 1) s += __shfl_down_sync(0xffffffffu, s, o);
    if (lane == 0) lg[w] = s;
    __syncthreads();

    if (tid == 0) {
        #pragma unroll
        for (int e = 0; e < NE; e++) logits[t * NE + e] = lg[e];
        // top-2 (strict > keeps lowest index on ties, matching lax.top_k)
        int e0 = 0; float l0 = lg[0];
        for (int e = 1; e < NE; e++) if (lg[e] > l0) { l0 = lg[e]; e0 = e; }
        int e1 = -1; float l1 = -1e30f;
        for (int e = 0; e < NE; e++) if (e != e0 && lg[e] > l1) { l1 = lg[e]; e1 = e; }
        // renormalized top-2 softmax weights: p0/(p0+p1) = sigmoid(l0-l1)
        float w0 = 1.f / (1.f + __expf(l1 - l0));
        float w1 = 1.f - w0;
        int p0 = atomicAdd(&g_counts[e0], 1);
        int p1 = atomicAdd(&g_counts[e1], 1);
        g_rows[e0 * CAP + p0] = t;
        g_rows[e1 * CAP + p1] = t;
        g_tok_e[2 * t] = e0;  g_tok_e[2 * t + 1] = e1;
        g_tok_p[2 * t] = p0;  g_tok_p[2 * t + 1] = p1;
        g_tok_w[2 * t] = w0;  g_tok_w[2 * t + 1] = w1;
    }
}

// ---------------- 2) grouped GEMM1: h = silu(X W1) * (X W2) ---------------
// Tile 64x64x16, 256 threads, 4x4 per thread, dual-B, f32x2 accumulate.
__global__ __launch_bounds__(256) void gemm1_k(const float* __restrict__ x,
                                               const float* __restrict__ w1,
                                               const float* __restrict__ w2,
                                               const float* __restrict__ sw1,
                                               const float* __restrict__ sw2) {
    int g = blockIdx.z;
    int n = (g == 8) ? TOK : g_counts[g];
    int row0 = blockIdx.y * 64;
    if (row0 >= n) return;
    int col0 = blockIdx.x * 64;
    const float* B1 = (g == 8) ? sw1 : w1 + (size_t)g * DIM * HID;
    const float* B2 = (g == 8) ? sw2 : w2 + (size_t)g * DIM * HID;

    __shared__ float As[16 * 68];   // [k][row], stride 68 (bank-safe, 16B aligned)
    __shared__ float Bs1[16 * 64];
    __shared__ float Bs2[16 * 64];
    __shared__ int   toks[64];

    int tid = threadIdx.x;
    if (tid < 64) {
        int r = row0 + tid;
        toks[tid] = (r < n) ? ((g == 8) ? r : g_rows[g * CAP + r]) : -1;
    }
    __syncthreads();

    int ka = tid & 15, ra = tid >> 4;          // A-load coords
    int kb = tid >> 4, cb = (tid & 15) * 4;    // B-load coords
    int tx4 = (tid & 15) * 4, ry4 = (tid >> 4) * 4;

    const float* aptr[4];
    #pragma unroll
    for (int it = 0; it < 4; it++) {
        int tok = toks[ra + it * 16];
        aptr[it] = (tok >= 0) ? (x + (size_t)tok * DIM + ka) : (const float*)0;
    }

    unsigned long long acc1[4][2], acc2[4][2];
    #pragma unroll
    for (int i = 0; i < 4; i++) {
        acc1[i][0] = acc1[i][1] = 0ull;
        acc2[i][0] = acc2[i][1] = 0ull;
    }

    for (int k0 = 0; k0 < DIM; k0 += 16) {
        #pragma unroll
        for (int it = 0; it < 4; it++) {
            int rr = ra + it * 16;
            As[ka * 68 + rr] = aptr[it] ? aptr[it][k0] : 0.f;
        }
        float4 b1v = *(const float4*)(B1 + (size_t)(k0 + kb) * HID + col0 + cb);
        float4 b2v = *(const float4*)(B2 + (size_t)(k0 + kb) * HID + col0 + cb);
        *(float4*)&Bs1[kb * 64 + cb] = b1v;
        *(float4*)&Bs2[kb * 64 + cb] = b2v;
        __syncthreads();

        #pragma unroll
        for (int kk = 0; kk < 16; kk++) {
            float4 av = *(const float4*)&As[kk * 68 + ry4];
            unsigned long long pa[4];
            pa[0] = bcast2(av.x); pa[1] = bcast2(av.y);
            pa[2] = bcast2(av.z); pa[3] = bcast2(av.w);
            const unsigned long long* b1p = (const unsigned long long*)&Bs1[kk * 64 + tx4];
            const unsigned long long* b2p = (const unsigned long long*)&Bs2[kk * 64 + tx4];
            unsigned long long b10 = b1p[0], b11 = b1p[1];
            unsigned long long b20 = b2p[0], b21 = b2p[1];
            #pragma unroll
            for (int i = 0; i < 4; i++) {
                fma2(acc1[i][0], pa[i], b10); fma2(acc1[i][1], pa[i], b11);
                fma2(acc2[i][0], pa[i], b20); fma2(acc2[i][1], pa[i], b21);
            }
        }
        __syncthreads();
    }

    #pragma unroll
    for (int i = 0; i < 4; i++) {
        int r = row0 + ry4 + i;
        if (r >= n) continue;
        float* hp = g_hidden + ((size_t)g * CAP + r) * HID + col0 + tx4;
        #pragma unroll
        for (int p = 0; p < 2; p++) {
            float2 u = up2(acc1[i][p]);
            float2 v = up2(acc2[i][p]);
            float2 o;
            o.x = (u.x / (1.f + __expf(-u.x))) * v.x;
            o.y = (u.y / (1.f + __expf(-u.y))) * v.y;
            *(float2*)(hp + 2 * p) = o;
        }
    }
}

// ---------------- 3) grouped GEMM2: y = h W3 -------------------------------
__global__ __launch_bounds__(256) void gemm2_k(const float* __restrict__ w3,
                                               const float* __restrict__ sw3) {
    int g = blockIdx.z;
    int n = (g == 8) ? TOK : g_counts[g];
    int row0 = blockIdx.y * 64;
    if (row0 >= n) return;
    int col0 = blockIdx.x * 64;
    const float* B = (g == 8) ? sw3 : w3 + (size_t)g * HID * DIM;

    __shared__ float As[16 * 68];
    __shared__ float Bs[16 * 64];

    int tid = threadIdx.x;
    int ka = tid & 15, ra = tid >> 4;
    int kb = tid >> 4, cb = (tid & 15) * 4;
    int tx4 = (tid & 15) * 4, ry4 = (tid >> 4) * 4;

    const float* aptr[4];
    #pragma unroll
    for (int it = 0; it < 4; it++) {
        int r = row0 + ra + it * 16;
        aptr[it] = (r < n) ? (g_hidden + ((size_t)g * CAP + r) * HID + ka)
                           : (const float*)0;
    }

    unsigned long long acc[4][2];
    #pragma unroll
    for (int i = 0; i < 4; i++) { acc[i][0] = acc[i][1] = 0ull; }

    for (int k0 = 0; k0 < HID; k0 += 16) {
        #pragma unroll
        for (int it = 0; it < 4; it++) {
            int rr = ra + it * 16;
            As[ka * 68 + rr] = aptr[it] ? aptr[it][k0] : 0.f;
        }
        float4 bv = *(const float4*)(B + (size_t)(k0 + kb) * DIM + col0 + cb);
        *(float4*)&Bs[kb * 64 + cb] = bv;
        __syncthreads();

        #pragma unroll
        for (int kk = 0; kk < 16; kk++) {
            float4 av = *(const float4*)&As[kk * 68 + ry4];
            unsigned long long pa[4];
            pa[0] = bcast2(av.x); pa[1] = bcast2(av.y);
            pa[2] = bcast2(av.z); pa[3] = bcast2(av.w);
            const unsigned long long* bp = (const unsigned long long*)&Bs[kk * 64 + tx4];
            unsigned long long b0 = bp[0], b1 = bp[1];
            #pragma unroll
            for (int i = 0; i < 4; i++) {
                fma2(acc[i][0], pa[i], b0);
                fma2(acc[i][1], pa[i], b1);
            }
        }
        __syncthreads();
    }

    #pragma unroll
    for (int i = 0; i < 4; i++) {
        int r = row0 + ry4 + i;
        if (r >= n) continue;
        float* yp = g_y + ((size_t)g * CAP + r) * DIM + col0 + tx4;
        #pragma unroll
        for (int p = 0; p < 2; p++) {
            float2 u = up2(acc[i][p]);
            *(float2*)(yp + 2 * p) = u;
        }
    }
}

// ---------------- 4) combine: out = shared + w0*y_e0 + w1*y_e1 -------------
__global__ __launch_bounds__(256) void combine_k(float* __restrict__ out) {
    int t = blockIdx.x;
    int tid = threadIdx.x;
    int e0 = g_tok_e[2 * t], e1 = g_tok_e[2 * t + 1];
    int p0 = g_tok_p[2 * t], p1 = g_tok_p[2 * t + 1];
    float w0 = g_tok_w[2 * t], w1 = g_tok_w[2 * t + 1];

    const float4* ys = (const float4*)(g_y + ((size_t)8 * CAP + t) * DIM);
    const float4* y0 = (const float4*)(g_y + ((size_t)e0 * CAP + p0) * DIM);
    const float4* y1 = (const float4*)(g_y + ((size_t)e1 * CAP + p1) * DIM);
    float4* op = (float4*)(out + (size_t)t * DIM);

    // D/4 = 256 float4 per row, exactly one per thread
    float4 a = ys[tid], b = y0[tid], c = y1[tid];
    float4 o;
    o.x = a.x + w0 * b.x + w1 * c.x;
    o.y = a.y + w0 * b.y + w1 * c.y;
    o.z = a.z + w0 * b.z + w1 * c.z;
    o.w = a.w + w0 * b.w + w1 * c.w;
    op[tid] = o;
}

// ---------------- launch ---------------------------------------------------
extern "C" void kernel_launch(void* const* d_in, const int* in_sizes, int n_in,
                              void* d_out, int out_size) {
    const float* x   = (const float*)d_in[0];
    const float* sw1 = (const float*)d_in[1];
    const float* sw2 = (const float*)d_in[2];
    const float* sw3 = (const float*)d_in[3];
    const float* w1  = (const float*)d_in[4];
    const float* w2  = (const float*)d_in[5];
    const float* w3  = (const float*)d_in[6];
    const float* rw  = (const float*)d_in[7];
    float* out    = (float*)d_out;
    float* logits = out + (size_t)TOK * DIM;  // tuple (out, logits) flattened

    void* cptr = nullptr;
    cudaGetSymbolAddress(&cptr, g_counts);
    cudaMemsetAsync(cptr, 0, NE * sizeof(int));

    router_k<<<TOK, 256>>>(x, rw, logits);
    gemm1_k<<<dim3(HID / 64, CAP / 64, NG), 256>>>(x, w1, w2, sw1, sw2);
    gemm2_k<<<dim3(DIM / 64, CAP / 64, NG), 256>>>(w3, sw3);
    combine_k<<<TOK, 256>>>(out);
}

// round 3
// speedup vs baseline: 2.2842x; 2.2842x over previous
#include <cuda_runtime.h>
#include <math.h>
#include <stdint.h>

// Problem constants
#define TOK 2048
#define DIM 1024
#define HID 4096
#define NE  8
#define NG  9
#define CAP 2048

// GEMM tiling
#define MT 128
#define NT 128
#define KT 32
#define ASTR 36               // A smem row stride (floats), conflict-free frag loads
#define BSTR 132              // B smem row stride (floats)
#define ABYTES (MT * ASTR * 4)      // 18432
#define BBYTES (KT * BSTR * 4)      // 16896
#define STG1 (ABYTES + 2 * BBYTES)  // 52224  (A + B1 + B2)
#define STG2 (ABYTES + BBYTES)      // 35328  (A + B)
#define SMEM1 (3 * STG1)
#define SMEM2 (3 * STG2)

// ---------------- device scratch ----------------
__device__ int   g_counts[NE];
__device__ int   g_rows[NE * CAP];
__device__ int   g_tok_e[TOK * 2];
__device__ int   g_tok_p[TOK * 2];
__device__ float g_tok_w[TOK * 2];
__device__ float g_hidden[(size_t)NG * CAP * HID];
__device__ float g_y[(size_t)NG * CAP * DIM];

// ---------------- PTX helpers ----------------
__device__ __forceinline__ uint32_t smem_u32(const void* p) {
    uint32_t a;
    asm("{ .reg .u64 t; cvta.to.shared.u64 t, %1; cvt.u32.u64 %0, t; }"
        : "=r"(a) : "l"(p));
    return a;
}
__device__ __forceinline__ void cpa16(uint32_t dst, const float* src) {
    asm volatile("cp.async.cg.shared.global [%0], [%1], 16;"
                 :: "r"(dst), "l"(src) : "memory");
}
__device__ __forceinline__ void cpa16z(uint32_t dst, const float* src, int sz) {
    asm volatile("cp.async.cg.shared.global [%0], [%1], 16, %2;"
                 :: "r"(dst), "l"(src), "r"(sz) : "memory");
}
#define CP_COMMIT() asm volatile("cp.async.commit_group;" ::: "memory")
#define CP_WAIT2()  asm volatile("cp.async.wait_group 2;" ::: "memory")

__device__ __forceinline__ uint32_t f2t(float f) {
    uint32_t r;
    asm("cvt.rna.tf32.f32 %0, %1;" : "=r"(r) : "f"(f));
    return r;
}
__device__ __forceinline__ void mma8(float* d, const uint32_t* a, const uint32_t* b) {
    asm volatile(
        "mma.sync.aligned.m16n8k8.row.col.f32.tf32.tf32.f32 "
        "{%0,%1,%2,%3}, {%4,%5,%6,%7}, {%8,%9}, {%0,%1,%2,%3};"
        : "+f"(d[0]), "+f"(d[1]), "+f"(d[2]), "+f"(d[3])
        : "r"(a[0]), "r"(a[1]), "r"(a[2]), "r"(a[3]), "r"(b[0]), "r"(b[1]));
}

// ---------------- 1) router ----------------
__global__ __launch_bounds__(256) void router_k(const float* __restrict__ x,
                                                const float* __restrict__ rw,
                                                float* __restrict__ logits) {
    int t = blockIdx.x;
    __shared__ float xs[DIM];
    __shared__ float lg[NE];
    int tid = threadIdx.x;
    for (int i = tid; i < DIM; i += 256) xs[i] = x[(size_t)t * DIM + i];
    __syncthreads();
    int w = tid >> 5, lane = tid & 31;
    const float* r = rw + w * DIM;
    float s = 0.f;
    for (int i = lane; i < DIM; i += 32) s += xs[i] * r[i];
    #pragma unroll
    for (int o = 16; o; o >>= 1) s += __shfl_down_sync(0xffffffffu, s, o);
    if (lane == 0) lg[w] = s;
    __syncthreads();
    if (tid == 0) {
        #pragma unroll
        for (int e = 0; e < NE; e++) logits[t * NE + e] = lg[e];
        int e0 = 0; float l0 = lg[0];
        for (int e = 1; e < NE; e++) if (lg[e] > l0) { l0 = lg[e]; e0 = e; }
        int e1 = -1; float l1 = -1e30f;
        for (int e = 0; e < NE; e++) if (e != e0 && lg[e] > l1) { l1 = lg[e]; e1 = e; }
        float w0 = 1.f / (1.f + __expf(l1 - l0));
        float w1 = 1.f - w0;
        int p0 = atomicAdd(&g_counts[e0], 1);
        int p1 = atomicAdd(&g_counts[e1], 1);
        g_rows[e0 * CAP + p0] = t;
        g_rows[e1 * CAP + p1] = t;
        g_tok_e[2*t] = e0; g_tok_e[2*t+1] = e1;
        g_tok_p[2*t] = p0; g_tok_p[2*t+1] = p1;
        g_tok_w[2*t] = w0; g_tok_w[2*t+1] = w1;
    }
}

// ---------------- 2) GEMM1 (tf32 mma.sync): h = silu(X W1) * (X W2) --------
__global__ __launch_bounds__(256, 1) void gemm1_tc(const float* __restrict__ x,
                                                   const float* __restrict__ w1,
                                                   const float* __restrict__ w2,
                                                   const float* __restrict__ sw1,
                                                   const float* __restrict__ sw2) {
    int g = blockIdx.z;
    int n = (g == 8) ? TOK : g_counts[g];
    int row0 = blockIdx.x * MT;
    if (row0 >= n) return;
    int col0 = blockIdx.y * NT;
    const float* B1g = (g == 8) ? sw1 : w1 + (size_t)g * DIM * HID;
    const float* B2g = (g == 8) ? sw2 : w2 + (size_t)g * DIM * HID;

    extern __shared__ float dynf[];
    __shared__ int toks[MT];
    int tid = threadIdx.x, lane = tid & 31, wid = tid >> 5;

    if (tid < MT) {
        int r = row0 + tid;
        toks[tid] = (r < n) ? ((g == 8) ? r : g_rows[g * CAP + r]) : -1;
    }
    __syncthreads();

    // producer coords
    int am = tid >> 1, aq = (tid & 1) * 4;
    int atok = toks[am];
    const float* asrc = ((atok >= 0) ? x + (size_t)atok * DIM : x) + aq * 4;
    int asz = (atok >= 0) ? 16 : 0;
    uint32_t sbase = smem_u32(dynf);
    uint32_t adst = sbase + am * (ASTR * 4) + aq * 16;
    int bk = tid >> 3, bq8 = tid & 7;
    const float* b1src = B1g + col0 + bq8 * 16;
    const float* b2src = B2g + col0 + bq8 * 16;
    uint32_t bdst = sbase + ABYTES + bk * (BSTR * 4) + bq8 * 64;

    const int NC = DIM / KT;  // 32

    auto prefetch = [&](int c) {
        uint32_t so = (uint32_t)(c % 3) * STG1;
        int k0 = c * KT;
        #pragma unroll
        for (int j = 0; j < 4; j++)
            cpa16z(adst + so + j * 16, asrc + k0 + j * 4, asz);
        const float* bp1 = b1src + (size_t)(k0 + bk) * HID;
        const float* bp2 = b2src + (size_t)(k0 + bk) * HID;
        #pragma unroll
        for (int j = 0; j < 4; j++) cpa16(bdst + so + j * 16, bp1 + j * 4);
        #pragma unroll
        for (int j = 0; j < 4; j++) cpa16(bdst + so + BBYTES + j * 16, bp2 + j * 4);
    };

    prefetch(0); CP_COMMIT();
    prefetch(1); CP_COMMIT();

    float acc1[4][4][4] = {};
    float acc2[4][4][4] = {};
    int wm = (wid & 1) * 64, wn = (wid >> 1) * 32;

    for (int c = 0; c < NC; c++) {
        if (c + 2 < NC) prefetch(c + 2);
        CP_COMMIT();
        CP_WAIT2();
        __syncthreads();
        const float* As  = dynf + (size_t)(c % 3) * (STG1 / 4);
        const float* Bs1 = As + ABYTES / 4;
        const float* Bs2 = Bs1 + BBYTES / 4;
        #pragma unroll
        for (int kk = 0; kk < 4; kk++) {
            uint32_t af[4][4];
            #pragma unroll
            for (int mf = 0; mf < 4; mf++) {
                const float* ap = As + (wm + mf * 16 + (lane >> 2)) * ASTR + kk * 8 + (lane & 3);
                af[mf][0] = f2t(ap[0]);
                af[mf][1] = f2t(ap[8 * ASTR]);
                af[mf][2] = f2t(ap[4]);
                af[mf][3] = f2t(ap[8 * ASTR + 4]);
            }
            #pragma unroll
            for (int nf = 0; nf < 4; nf++) {
                const float* bp1 = Bs1 + (kk * 8 + (lane & 3)) * BSTR + wn + nf * 8 + (lane >> 2);
                const float* bp2 = Bs2 + (kk * 8 + (lane & 3)) * BSTR + wn + nf * 8 + (lane >> 2);
                uint32_t b1[2] = { f2t(bp1[0]), f2t(bp1[4 * BSTR]) };
                uint32_t b2[2] = { f2t(bp2[0]), f2t(bp2[4 * BSTR]) };
                #pragma unroll
                for (int mf = 0; mf < 4; mf++) {
                    mma8(acc1[mf][nf], af[mf], b1);
                    mma8(acc2[mf][nf], af[mf], b2);
                }
            }
        }
        __syncthreads();
    }

    // epilogue: silu(acc1)*acc2 -> g_hidden
    #pragma unroll
    for (int mf = 0; mf < 4; mf++) {
        #pragma unroll
        for (int h = 0; h < 2; h++) {
            int r = row0 + wm + mf * 16 + (lane >> 2) + h * 8;
            if (r < n) {
                float* hp = g_hidden + ((size_t)g * CAP + r) * HID + col0 + wn;
                #pragma unroll
                for (int nf = 0; nf < 4; nf++) {
                    float a0 = acc1[mf][nf][h * 2], a1 = acc1[mf][nf][h * 2 + 1];
                    float s0 = a0 / (1.f + __expf(-a0));
                    float s1 = a1 / (1.f + __expf(-a1));
                    float2 o = make_float2(s0 * acc2[mf][nf][h * 2],
                                           s1 * acc2[mf][nf][h * 2 + 1]);
                    *(float2*)(hp + nf * 8 + (lane & 3) * 2) = o;
                }
            }
        }
    }
}

// ---------------- 3) GEMM2 (tf32 mma.sync): y = h W3 -----------------------
__global__ __launch_bounds__(256, 1) void gemm2_tc(const float* __restrict__ w3,
                                                   const float* __restrict__ sw3) {
    int g = blockIdx.z;
    int n = (g == 8) ? TOK : g_counts[g];
    int row0 = blockIdx.x * MT;
    if (row0 >= n) return;
    int col0 = blockIdx.y * NT;
    const float* Bg = (g == 8) ? sw3 : w3 + (size_t)g * HID * DIM;

    extern __shared__ float dynf[];
    int tid = threadIdx.x, lane = tid & 31, wid = tid >> 5;

    int am = tid >> 1, aq = (tid & 1) * 4;
    int ar = row0 + am;
    const float* asrc = ((ar < n) ? g_hidden + ((size_t)g * CAP + ar) * HID
                                  : g_hidden) + aq * 4;
    int asz = (ar < n) ? 16 : 0;
    uint32_t sbase = smem_u32(dynf);
    uint32_t adst = sbase + am * (ASTR * 4) + aq * 16;
    int bk = tid >> 3, bq8 = tid & 7;
    const float* bsrc = Bg + col0 + bq8 * 16;
    uint32_t bdst = sbase + ABYTES + bk * (BSTR * 4) + bq8 * 64;

    const int NC = HID / KT;  // 128

    auto prefetch = [&](int c) {
        uint32_t so = (uint32_t)(c % 3) * STG2;
        int k0 = c * KT;
        #pragma unroll
        for (int j = 0; j < 4; j++)
            cpa16z(adst + so + j * 16, asrc + k0 + j * 4, asz);
        const float* bp = bsrc + (size_t)(k0 + bk) * DIM;
        #pragma unroll
        for (int j = 0; j < 4; j++) cpa16(bdst + so + j * 16, bp + j * 4);
    };

    prefetch(0); CP_COMMIT();
    prefetch(1); CP_COMMIT();

    float acc[4][4][4] = {};
    int wm = (wid & 1) * 64, wn = (wid >> 1) * 32;

    for (int c = 0; c < NC; c++) {
        if (c + 2 < NC) prefetch(c + 2);
        CP_COMMIT();
        CP_WAIT2();
        __syncthreads();
        const float* As = dynf + (size_t)(c % 3) * (STG2 / 4);
        const float* Bs = As + ABYTES / 4;
        #pragma unroll
        for (int kk = 0; kk < 4; kk++) {
            uint32_t af[4][4];
            #pragma unroll
            for (int mf = 0; mf < 4; mf++) {
                const float* ap = As + (wm + mf * 16 + (lane >> 2)) * ASTR + kk * 8 + (lane & 3);
                af[mf][0] = f2t(ap[0]);
                af[mf][1] = f2t(ap[8 * ASTR]);
                af[mf][2] = f2t(ap[4]);
                af[mf][3] = f2t(ap[8 * ASTR + 4]);
            }
            #pragma unroll
            for (int nf = 0; nf < 4; nf++) {
                const float* bp = Bs + (kk * 8 + (lane & 3)) * BSTR + wn + nf * 8 + (lane >> 2);
                uint32_t b[2] = { f2t(bp[0]), f2t(bp[4 * BSTR]) };
                #pragma unroll
                for (int mf = 0; mf < 4; mf++) mma8(acc[mf][nf], af[mf], b);
            }
        }
        __syncthreads();
    }

    #pragma unroll
    for (int mf = 0; mf < 4; mf++) {
        #pragma unroll
        for (int h = 0; h < 2; h++) {
            int r = row0 + wm + mf * 16 + (lane >> 2) + h * 8;
            if (r < n) {
                float* yp = g_y + ((size_t)g * CAP + r) * DIM + col0 + wn;
                #pragma unroll
                for (int nf = 0; nf < 4; nf++) {
                    float2 o = make_float2(acc[mf][nf][h * 2], acc[mf][nf][h * 2 + 1]);
                    *(float2*)(yp + nf * 8 + (lane & 3) * 2) = o;
                }
            }
        }
    }
}

// ---------------- 4) combine ----------------
__global__ __launch_bounds__(256) void combine_k(float* __restrict__ out) {
    int t = blockIdx.x;
    int tid = threadIdx.x;
    int e0 = g_tok_e[2*t], e1 = g_tok_e[2*t+1];
    int p0 = g_tok_p[2*t], p1 = g_tok_p[2*t+1];
    float w0 = g_tok_w[2*t], w1 = g_tok_w[2*t+1];
    const float4* ys = (const float4*)(g_y + ((size_t)8 * CAP + t) * DIM);
    const float4* y0 = (const float4*)(g_y + ((size_t)e0 * CAP + p0) * DIM);
    const float4* y1 = (const float4*)(g_y + ((size_t)e1 * CAP + p1) * DIM);
    float4* op = (float4*)(out + (size_t)t * DIM);
    float4 a = ys[tid], b = y0[tid], c = y1[tid];
    float4 o;
    o.x = a.x + w0 * b.x + w1 * c.x;
    o.y = a.y + w0 * b.y + w1 * c.y;
    o.z = a.z + w0 * b.z + w1 * c.z;
    o.w = a.w + w0 * b.w + w1 * c.w;
    op[tid] = o;
}

// ---------------- launch ----------------
extern "C" void kernel_launch(void* const* d_in, const int* in_sizes, int n_in,
                              void* d_out, int out_size) {
    const float* x   = (const float*)d_in[0];
    const float* sw1 = (const float*)d_in[1];
    const float* sw2 = (const float*)d_in[2];
    const float* sw3 = (const float*)d_in[3];
    const float* w1  = (const float*)d_in[4];
    const float* w2  = (const float*)d_in[5];
    const float* w3  = (const float*)d_in[6];
    const float* rw  = (const float*)d_in[7];
    float* out    = (float*)d_out;
    float* logits = out + (size_t)TOK * DIM;

    cudaFuncSetAttribute(gemm1_tc, cudaFuncAttributeMaxDynamicSharedMemorySize, SMEM1);
    cudaFuncSetAttribute(gemm2_tc, cudaFuncAttributeMaxDynamicSharedMemorySize, SMEM2);

    void* cptr = nullptr;
    cudaGetSymbolAddress(&cptr, g_counts);
    cudaMemsetAsync(cptr, 0, NE * sizeof(int));

    router_k<<<TOK, 256>>>(x, rw, logits);
    gemm1_tc<<<dim3(CAP / MT, HID / NT, NG), 256, SMEM1>>>(x, w1, w2, sw1, sw2);
    gemm2_tc<<<dim3(CAP / MT, DIM / NT, NG), 256, SMEM2>>>(w3, sw3);
    combine_k<<<TOK, 256>>>(out);
}

// round 4
// speedup vs baseline: 4.3611x; 1.9092x over previous
#include <cuda_runtime.h>
#include <cuda_fp16.h>
#include <math.h>
#include <stdint.h>

// Problem constants
#define TOK 2048
#define DIM 1024
#define HID 4096
#define NE  8
#define NG  9
#define CAP 2048

// GEMM tiling (fp16 mma m16n8k16)
#define MT 128
#define NT 128
#define KT 32
#define AS  40                 // A smem row stride in halves (80B)
#define BSH 136                // B smem row stride in halves (272B)
#define A_BYTES (MT * AS * 2)          // 10240
#define B_BYTES (KT * BSH * 2)         // 8704
#define STG1 (A_BYTES + 2 * B_BYTES)   // 27648
#define STG2 (A_BYTES + B_BYTES)       // 18944
#define SMEM1 (3 * STG1)
#define SMEM2 (3 * STG2)

// ---------------- device scratch ----------------
__device__ int    g_counts[NE];
__device__ int    g_rows[NE * CAP];
__device__ int    g_tok_e[TOK * 2];
__device__ int    g_tok_p[TOK * 2];
__device__ float  g_tok_w[TOK * 2];
__device__ __half g_xh[(size_t)TOK * DIM];
__device__ __half g_w1h[(size_t)NG * DIM * HID];
__device__ __half g_w2h[(size_t)NG * DIM * HID];
__device__ __half g_w3h[(size_t)NG * HID * DIM];
__device__ __half g_hh[(size_t)NG * CAP * HID];
__device__ float  g_y[(size_t)NG * CAP * DIM];

// ---------------- PTX helpers ----------------
__device__ __forceinline__ uint32_t smem_u32(const void* p) {
    uint32_t a;
    asm("{ .reg .u64 t; cvta.to.shared.u64 t, %1; cvt.u32.u64 %0, t; }"
        : "=r"(a) : "l"(p));
    return a;
}
__device__ __forceinline__ void cpa16(uint32_t dst, const void* src) {
    asm volatile("cp.async.cg.shared.global [%0], [%1], 16;"
                 :: "r"(dst), "l"(src) : "memory");
}
__device__ __forceinline__ void cpa16z(uint32_t dst, const void* src, int sz) {
    asm volatile("cp.async.cg.shared.global [%0], [%1], 16, %2;"
                 :: "r"(dst), "l"(src), "r"(sz) : "memory");
}
#define CP_COMMIT() asm volatile("cp.async.commit_group;" ::: "memory")
#define CP_WAIT2()  asm volatile("cp.async.wait_group 2;" ::: "memory")

__device__ __forceinline__ void ldsm4(uint32_t* r, uint32_t addr) {
    asm volatile("ldmatrix.sync.aligned.m8n8.x4.shared.b16 {%0,%1,%2,%3}, [%4];"
                 : "=r"(r[0]), "=r"(r[1]), "=r"(r[2]), "=r"(r[3]) : "r"(addr));
}
__device__ __forceinline__ void ldsm4t(uint32_t* r, uint32_t addr) {
    asm volatile("ldmatrix.sync.aligned.m8n8.x4.trans.shared.b16 {%0,%1,%2,%3}, [%4];"
                 : "=r"(r[0]), "=r"(r[1]), "=r"(r[2]), "=r"(r[3]) : "r"(addr));
}
__device__ __forceinline__ void mma16(float* d, const uint32_t* a, const uint32_t* b) {
    asm volatile(
        "mma.sync.aligned.m16n8k16.row.col.f32.f16.f16.f32 "
        "{%0,%1,%2,%3}, {%4,%5,%6,%7}, {%8,%9}, {%0,%1,%2,%3};"
        : "+f"(d[0]), "+f"(d[1]), "+f"(d[2]), "+f"(d[3])
        : "r"(a[0]), "r"(a[1]), "r"(a[2]), "r"(a[3]), "r"(b[0]), "r"(b[1]));
}

// ---------------- 0) convert f32 -> f16 ----------------
__global__ __launch_bounds__(256) void convert_k(
    const float* __restrict__ x,
    const float* __restrict__ sw1, const float* __restrict__ sw2,
    const float* __restrict__ sw3,
    const float* __restrict__ w1, const float* __restrict__ w2,
    const float* __restrict__ w3) {
    int seg = blockIdx.y;
    const float* src; __half* dst; size_t cnt;
    switch (seg) {
        case 0: src = w1;  dst = g_w1h;                        cnt = (size_t)NE * DIM * HID; break;
        case 1: src = sw1; dst = g_w1h + (size_t)NE * DIM * HID; cnt = (size_t)DIM * HID;    break;
        case 2: src = w2;  dst = g_w2h;                        cnt = (size_t)NE * DIM * HID; break;
        case 3: src = sw2; dst = g_w2h + (size_t)NE * DIM * HID; cnt = (size_t)DIM * HID;    break;
        case 4: src = w3;  dst = g_w3h;                        cnt = (size_t)NE * HID * DIM; break;
        case 5: src = sw3; dst = g_w3h + (size_t)NE * HID * DIM; cnt = (size_t)HID * DIM;    break;
        default: src = x;  dst = g_xh;                         cnt = (size_t)TOK * DIM;      break;
    }
    size_t n4 = cnt >> 2;
    size_t i0 = (size_t)blockIdx.x * blockDim.x + threadIdx.x;
    size_t stride = (size_t)gridDim.x * blockDim.x;
    const float4* s4 = (const float4*)src;
    __half2* d2 = (__half2*)dst;
    for (size_t i = i0; i < n4; i += stride) {
        float4 v = s4[i];
        d2[2 * i]     = __floats2half2_rn(v.x, v.y);
        d2[2 * i + 1] = __floats2half2_rn(v.z, v.w);
    }
}

// ---------------- 1) router ----------------
__global__ __launch_bounds__(256) void router_k(const float* __restrict__ x,
                                                const float* __restrict__ rw,
                                                float* __restrict__ logits) {
    int t = blockIdx.x;
    __shared__ float xs[DIM];
    __shared__ float lg[NE];
    int tid = threadIdx.x;
    for (int i = tid; i < DIM; i += 256) xs[i] = x[(size_t)t * DIM + i];
    __syncthreads();
    int w = tid >> 5, lane = tid & 31;
    const float* r = rw + w * DIM;
    float s = 0.f;
    for (int i = lane; i < DIM; i += 32) s += xs[i] * r[i];
    #pragma unroll
    for (int o = 16; o; o >>= 1) s += __shfl_down_sync(0xffffffffu, s, o);
    if (lane == 0) lg[w] = s;
    __syncthreads();
    if (tid == 0) {
        #pragma unroll
        for (int e = 0; e < NE; e++) logits[t * NE + e] = lg[e];
        int e0 = 0; float l0 = lg[0];
        for (int e = 1; e < NE; e++) if (lg[e] > l0) { l0 = lg[e]; e0 = e; }
        int e1 = -1; float l1 = -1e30f;
        for (int e = 0; e < NE; e++) if (e != e0 && lg[e] > l1) { l1 = lg[e]; e1 = e; }
        float w0 = 1.f / (1.f + __expf(l1 - l0));
        float w1 = 1.f - w0;
        int p0 = atomicAdd(&g_counts[e0], 1);
        int p1 = atomicAdd(&g_counts[e1], 1);
        g_rows[e0 * CAP + p0] = t;
        g_rows[e1 * CAP + p1] = t;
        g_tok_e[2*t] = e0; g_tok_e[2*t+1] = e1;
        g_tok_p[2*t] = p0; g_tok_p[2*t+1] = p1;
        g_tok_w[2*t] = w0; g_tok_w[2*t+1] = w1;
    }
}

// ---------------- 2) GEMM1 (fp16 mma): h = silu(X W1) * (X W2) -------------
__global__ __launch_bounds__(256, 1) void gemm1_tc() {
    int g = blockIdx.z;
    int n = (g == 8) ? TOK : g_counts[g];
    int row0 = blockIdx.x * MT;
    if (row0 >= n) return;
    int col0 = blockIdx.y * NT;
    const __half* B1g = g_w1h + (size_t)g * DIM * HID;
    const __half* B2g = g_w2h + (size_t)g * DIM * HID;

    extern __shared__ char dynb[];
    __shared__ int toks[MT];
    int tid = threadIdx.x, lane = tid & 31, wid = tid >> 5;

    if (tid < MT) {
        int r = row0 + tid;
        toks[tid] = (r < n) ? ((g == 8) ? r : g_rows[g * CAP + r]) : -1;
    }
    __syncthreads();

    uint32_t sbase = smem_u32(dynb);
    // producer coords
    int am = tid >> 1, aq = (tid & 1) * 2;   // 2 chunks of 16B per thread
    int atok = toks[am];
    const __half* asrc = g_xh + ((atok >= 0) ? (size_t)atok * DIM : 0) + aq * 8;
    int asz = (atok >= 0) ? 16 : 0;
    uint32_t adst = sbase + am * (AS * 2) + aq * 16;
    int brow = tid >> 3, bch = (tid & 7) * 2;
    const __half* b1src = B1g + (size_t)brow * HID + col0 + bch * 8;
    const __half* b2src = B2g + (size_t)brow * HID + col0 + bch * 8;
    uint32_t bdst = sbase + A_BYTES + brow * (BSH * 2) + bch * 16;

    const int NC = DIM / KT;  // 32

    auto prefetch = [&](int c) {
        uint32_t so = (uint32_t)(c % 3) * STG1;
        cpa16z(adst + so,      asrc + c * 32,     asz);
        cpa16z(adst + so + 16, asrc + c * 32 + 8, asz);
        const __half* p1 = b1src + (size_t)(c * 32) * HID;
        const __half* p2 = b2src + (size_t)(c * 32) * HID;
        cpa16(bdst + so,                p1);
        cpa16(bdst + so + 16,           p1 + 8);
        cpa16(bdst + so + B_BYTES,      p2);
        cpa16(bdst + so + B_BYTES + 16, p2 + 8);
    };

    prefetch(0); CP_COMMIT();
    prefetch(1); CP_COMMIT();

    float acc1[4][4][4] = {};
    float acc2[4][4][4] = {};
    int wm = (wid & 1) * 64, wn = (wid >> 1) * 32;
    uint32_t aoff = ((wm + (lane & 15)) * AS + (lane >> 4) * 8) * 2;
    uint32_t boff = ((lane & 15) * BSH + wn + (lane >> 4) * 8) * 2;

    for (int c = 0; c < NC; c++) {
        if (c + 2 < NC) prefetch(c + 2);
        CP_COMMIT();
        CP_WAIT2();
        __syncthreads();
        uint32_t As_u = sbase + (uint32_t)(c % 3) * STG1;
        uint32_t B1_u = As_u + A_BYTES;
        uint32_t B2_u = B1_u + B_BYTES;
        #pragma unroll
        for (int kk = 0; kk < 2; kk++) {
            uint32_t af[4][4];
            #pragma unroll
            for (int mf = 0; mf < 4; mf++)
                ldsm4(af[mf], As_u + aoff + mf * (16 * AS * 2) + kk * 32);
            #pragma unroll
            for (int nfp = 0; nfp < 2; nfp++) {
                uint32_t bb = boff + nfp * 32 + kk * (16 * BSH * 2);
                uint32_t b1[4], b2[4];
                ldsm4t(b1, B1_u + bb);
                ldsm4t(b2, B2_u + bb);
                #pragma unroll
                for (int mf = 0; mf < 4; mf++) {
                    mma16(acc1[mf][nfp * 2],     af[mf], b1);
                    mma16(acc1[mf][nfp * 2 + 1], af[mf], b1 + 2);
                    mma16(acc2[mf][nfp * 2],     af[mf], b2);
                    mma16(acc2[mf][nfp * 2 + 1], af[mf], b2 + 2);
                }
            }
        }
        __syncthreads();
    }

    // epilogue: silu(acc1)*acc2 -> g_hh (fp16)
    #pragma unroll
    for (int mf = 0; mf < 4; mf++) {
        #pragma unroll
        for (int h = 0; h < 2; h++) {
            int r = row0 + wm + mf * 16 + (lane >> 2) + h * 8;
            if (r < n) {
                __half* hp = g_hh + ((size_t)g * CAP + r) * HID + col0 + wn + (lane & 3) * 2;
                #pragma unroll
                for (int nf = 0; nf < 4; nf++) {
                    float a0 = acc1[mf][nf][h * 2], a1 = acc1[mf][nf][h * 2 + 1];
                    float s0 = a0 / (1.f + __expf(-a0));
                    float s1 = a1 / (1.f + __expf(-a1));
                    *(__half2*)(hp + nf * 8) =
                        __floats2half2_rn(s0 * acc2[mf][nf][h * 2],
                                          s1 * acc2[mf][nf][h * 2 + 1]);
                }
            }
        }
    }
}

// ---------------- 3) GEMM2 (fp16 mma): y = h W3 ----------------------------
__global__ __launch_bounds__(256, 1) void gemm2_tc() {
    int g = blockIdx.z;
    int n = (g == 8) ? TOK : g_counts[g];
    int row0 = blockIdx.x * MT;
    if (row0 >= n) return;
    int col0 = blockIdx.y * NT;
    const __half* Bg = g_w3h + (size_t)g * HID * DIM;

    extern __shared__ char dynb[];
    int tid = threadIdx.x, lane = tid & 31, wid = tid >> 5;
    uint32_t sbase = smem_u32(dynb);

    int am = tid >> 1, aq = (tid & 1) * 2;
    int ar = row0 + am;
    const __half* asrc = g_hh + ((ar < n) ? ((size_t)g * CAP + ar) * HID : 0) + aq * 8;
    int asz = (ar < n) ? 16 : 0;
    uint32_t adst = sbase + am * (AS * 2) + aq * 16;
    int brow = tid >> 3, bch = (tid & 7) * 2;
    const __half* bsrc = Bg + (size_t)brow * DIM + col0 + bch * 8;
    uint32_t bdst = sbase + A_BYTES + brow * (BSH * 2) + bch * 16;

    const int NC = HID / KT;  // 128

    auto prefetch = [&](int c) {
        uint32_t so = (uint32_t)(c % 3) * STG2;
        cpa16z(adst + so,      asrc + c * 32,     asz);
        cpa16z(adst + so + 16, asrc + c * 32 + 8, asz);
        const __half* p = bsrc + (size_t)(c * 32) * DIM;
        cpa16(bdst + so,      p);
        cpa16(bdst + so + 16, p + 8);
    };

    prefetch(0); CP_COMMIT();
    prefetch(1); CP_COMMIT();

    float acc[4][4][4] = {};
    int wm = (wid & 1) * 64, wn = (wid >> 1) * 32;
    uint32_t aoff = ((wm + (lane & 15)) * AS + (lane >> 4) * 8) * 2;
    uint32_t boff = ((lane & 15) * BSH + wn + (lane >> 4) * 8) * 2;

    for (int c = 0; c < NC; c++) {
        if (c + 2 < NC) prefetch(c + 2);
        CP_COMMIT();
        CP_WAIT2();
        __syncthreads();
        uint32_t As_u = sbase + (uint32_t)(c % 3) * STG2;
        uint32_t B_u  = As_u + A_BYTES;
        #pragma unroll
        for (int kk = 0; kk < 2; kk++) {
            uint32_t af[4][4];
            #pragma unroll
            for (int mf = 0; mf < 4; mf++)
                ldsm4(af[mf], As_u + aoff + mf * (16 * AS * 2) + kk * 32);
            #pragma unroll
            for (int nfp = 0; nfp < 2; nfp++) {
                uint32_t bb = boff + nfp * 32 + kk * (16 * BSH * 2);
                uint32_t b[4];
                ldsm4t(b, B_u + bb);
                #pragma unroll
                for (int mf = 0; mf < 4; mf++) {
                    mma16(acc[mf][nfp * 2],     af[mf], b);
                    mma16(acc[mf][nfp * 2 + 1], af[mf], b + 2);
                }
            }
        }
        __syncthreads();
    }

    #pragma unroll
    for (int mf = 0; mf < 4; mf++) {
        #pragma unroll
        for (int h = 0; h < 2; h++) {
            int r = row0 + wm + mf * 16 + (lane >> 2) + h * 8;
            if (r < n) {
                float* yp = g_y + ((size_t)g * CAP + r) * DIM + col0 + wn + (lane & 3) * 2;
                #pragma unroll
                for (int nf = 0; nf < 4; nf++)
                    *(float2*)(yp + nf * 8) =
                        make_float2(acc[mf][nf][h * 2], acc[mf][nf][h * 2 + 1]);
            }
        }
    }
}

// ---------------- 4) combine ----------------
__global__ __launch_bounds__(256) void combine_k(float* __restrict__ out) {
    int t = blockIdx.x;
    int tid = threadIdx.x;
    int e0 = g_tok_e[2*t], e1 = g_tok_e[2*t+1];
    int p0 = g_tok_p[2*t], p1 = g_tok_p[2*t+1];
    float w0 = g_tok_w[2*t], w1 = g_tok_w[2*t+1];
    const float4* ys = (const float4*)(g_y + ((size_t)8 * CAP + t) * DIM);
    const float4* y0 = (const float4*)(g_y + ((size_t)e0 * CAP + p0) * DIM);
    const float4* y1 = (const float4*)(g_y + ((size_t)e1 * CAP + p1) * DIM);
    float4* op = (float4*)(out + (size_t)t * DIM);
    float4 a = ys[tid], b = y0[tid], c = y1[tid];
    float4 o;
    o.x = a.x + w0 * b.x + w1 * c.x;
    o.y = a.y + w0 * b.y + w1 * c.y;
    o.z = a.z + w0 * b.z + w1 * c.z;
    o.w = a.w + w0 * b.w + w1 * c.w;
    op[tid] = o;
}

// ---------------- launch ----------------
extern "C" void kernel_launch(void* const* d_in, const int* in_sizes, int n_in,
                              void* d_out, int out_size) {
    const float* x   = (const float*)d_in[0];
    const float* sw1 = (const float*)d_in[1];
    const float* sw2 = (const float*)d_in[2];
    const float* sw3 = (const float*)d_in[3];
    const float* w1  = (const float*)d_in[4];
    const float* w2  = (const float*)d_in[5];
    const float* w3  = (const float*)d_in[6];
    const float* rw  = (const float*)d_in[7];
    float* out    = (float*)d_out;
    float* logits = out + (size_t)TOK * DIM;

    cudaFuncSetAttribute(gemm1_tc, cudaFuncAttributeMaxDynamicSharedMemorySize, SMEM1);
    cudaFuncSetAttribute(gemm2_tc, cudaFuncAttributeMaxDynamicSharedMemorySize, SMEM2);

    void* cptr = nullptr;
    cudaGetSymbolAddress(&cptr, g_counts);
    cudaMemsetAsync(cptr, 0, NE * sizeof(int));

    convert_k<<<dim3(864, 7), 256>>>(x, sw1, sw2, sw3, w1, w2, w3);
    router_k<<<TOK, 256>>>(x, rw, logits);
    gemm1_tc<<<dim3(CAP / MT, HID / NT, NG), 256, SMEM1>>>();
    gemm2_tc<<<dim3(CAP / MT, DIM / NT, NG), 256, SMEM2>>>();
    combine_k<<<TOK, 256>>>(out);
}

// round 5
// speedup vs baseline: 5.5084x; 1.2631x over previous
#include <cuda_runtime.h>
#include <cuda_fp16.h>
#include <math.h>
#include <stdint.h>

// Problem constants
#define TOK 2048
#define DIM 1024
#define HID 4096
#define NE  8
#define NG  9
#define CAP 2048

// GEMM tiling (fp16 mma m16n8k16)
#define MT 128
#define NT 128
#define KT 32
#define AS  40                 // A smem row stride in halves (80B)
#define BSH 136                // B smem row stride in halves (272B)
#define A_BYTES (MT * AS * 2)          // 10240
#define B_BYTES (KT * BSH * 2)         // 8704
#define STG1 (A_BYTES + 2 * B_BYTES)   // 27648
#define STG2 (A_BYTES + B_BYTES)       // 18944
#define SMEM1 (3 * STG1)               // 82944   (1 CTA x 512 thr)
#define SMEM2 (4 * STG2)               // 75776   (2 CTA x 256 thr)

// ---------------- device scratch ----------------
__device__ int    g_counts[NE];
__device__ int    g_rows[NE * CAP];
__device__ int    g_tok_e[TOK * 2];
__device__ int    g_tok_p[TOK * 2];
__device__ float  g_tok_w[TOK * 2];
__device__ __half g_xh[(size_t)TOK * DIM];
__device__ __half g_w1h[(size_t)NG * DIM * HID];
__device__ __half g_w2h[(size_t)NG * DIM * HID];
__device__ __half g_w3h[(size_t)NG * HID * DIM];
__device__ __half g_hh[(size_t)NG * CAP * HID];
__device__ float  g_y[(size_t)NG * CAP * DIM];

// ---------------- PTX helpers ----------------
__device__ __forceinline__ uint32_t smem_u32(const void* p) {
    uint32_t a;
    asm("{ .reg .u64 t; cvta.to.shared.u64 t, %1; cvt.u32.u64 %0, t; }"
        : "=r"(a) : "l"(p));
    return a;
}
__device__ __forceinline__ void cpa16(uint32_t dst, const void* src) {
    asm volatile("cp.async.cg.shared.global [%0], [%1], 16;"
                 :: "r"(dst), "l"(src) : "memory");
}
__device__ __forceinline__ void cpa16z(uint32_t dst, const void* src, int sz) {
    asm volatile("cp.async.cg.shared.global [%0], [%1], 16, %2;"
                 :: "r"(dst), "l"(src), "r"(sz) : "memory");
}
#define CP_COMMIT() asm volatile("cp.async.commit_group;" ::: "memory")
#define CP_WAIT(n)  asm volatile("cp.async.wait_group %0;" :: "n"(n) : "memory")

__device__ __forceinline__ void ldsm4(uint32_t* r, uint32_t addr) {
    asm volatile("ldmatrix.sync.aligned.m8n8.x4.shared.b16 {%0,%1,%2,%3}, [%4];"
                 : "=r"(r[0]), "=r"(r[1]), "=r"(r[2]), "=r"(r[3]) : "r"(addr));
}
__device__ __forceinline__ void ldsm4t(uint32_t* r, uint32_t addr) {
    asm volatile("ldmatrix.sync.aligned.m8n8.x4.trans.shared.b16 {%0,%1,%2,%3}, [%4];"
                 : "=r"(r[0]), "=r"(r[1]), "=r"(r[2]), "=r"(r[3]) : "r"(addr));
}
__device__ __forceinline__ void mma16(float* d, const uint32_t* a, const uint32_t* b) {
    asm volatile(
        "mma.sync.aligned.m16n8k16.row.col.f32.f16.f16.f32 "
        "{%0,%1,%2,%3}, {%4,%5,%6,%7}, {%8,%9}, {%0,%1,%2,%3};"
        : "+f"(d[0]), "+f"(d[1]), "+f"(d[2]), "+f"(d[3])
        : "r"(a[0]), "r"(a[1]), "r"(a[2]), "r"(a[3]), "r"(b[0]), "r"(b[1]));
}

// ---------------- 0) convert f32 -> f16 ----------------
__global__ __launch_bounds__(256) void convert_k(
    const float* __restrict__ x,
    const float* __restrict__ sw1, const float* __restrict__ sw2,
    const float* __restrict__ sw3,
    const float* __restrict__ w1, const float* __restrict__ w2,
    const float* __restrict__ w3) {
    int seg = blockIdx.y;
    const float* src; __half* dst; size_t cnt;
    switch (seg) {
        case 0: src = w1;  dst = g_w1h;                          cnt = (size_t)NE * DIM * HID; break;
        case 1: src = sw1; dst = g_w1h + (size_t)NE * DIM * HID; cnt = (size_t)DIM * HID;      break;
        case 2: src = w2;  dst = g_w2h;                          cnt = (size_t)NE * DIM * HID; break;
        case 3: src = sw2; dst = g_w2h + (size_t)NE * DIM * HID; cnt = (size_t)DIM * HID;      break;
        case 4: src = w3;  dst = g_w3h;                          cnt = (size_t)NE * HID * DIM; break;
        case 5: src = sw3; dst = g_w3h + (size_t)NE * HID * DIM; cnt = (size_t)HID * DIM;      break;
        default: src = x;  dst = g_xh;                           cnt = (size_t)TOK * DIM;      break;
    }
    size_t n4 = cnt >> 2;
    size_t i0 = (size_t)blockIdx.x * blockDim.x + threadIdx.x;
    size_t stride = (size_t)gridDim.x * blockDim.x;
    const float4* s4 = (const float4*)src;
    __half2* d2 = (__half2*)dst;
    for (size_t i = i0; i < n4; i += stride) {
        float4 v = s4[i];
        d2[2 * i]     = __floats2half2_rn(v.x, v.y);
        d2[2 * i + 1] = __floats2half2_rn(v.z, v.w);
    }
}

// ---------------- 1) router ----------------
__global__ __launch_bounds__(256) void router_k(const float* __restrict__ x,
                                                const float* __restrict__ rw,
                                                float* __restrict__ logits) {
    int t = blockIdx.x;
    __shared__ float xs[DIM];
    __shared__ float lg[NE];
    int tid = threadIdx.x;
    for (int i = tid; i < DIM; i += 256) xs[i] = x[(size_t)t * DIM + i];
    __syncthreads();
    int w = tid >> 5, lane = tid & 31;
    const float* r = rw + w * DIM;
    float s = 0.f;
    for (int i = lane; i < DIM; i += 32) s += xs[i] * r[i];
    #pragma unroll
    for (int o = 16; o; o >>= 1) s += __shfl_down_sync(0xffffffffu, s, o);
    if (lane == 0) lg[w] = s;
    __syncthreads();
    if (tid == 0) {
        #pragma unroll
        for (int e = 0; e < NE; e++) logits[t * NE + e] = lg[e];
        int e0 = 0; float l0 = lg[0];
        for (int e = 1; e < NE; e++) if (lg[e] > l0) { l0 = lg[e]; e0 = e; }
        int e1 = -1; float l1 = -1e30f;
        for (int e = 0; e < NE; e++) if (e != e0 && lg[e] > l1) { l1 = lg[e]; e1 = e; }
        float w0 = 1.f / (1.f + __expf(l1 - l0));
        float w1 = 1.f - w0;
        int p0 = atomicAdd(&g_counts[e0], 1);
        int p1 = atomicAdd(&g_counts[e1], 1);
        g_rows[e0 * CAP + p0] = t;
        g_rows[e1 * CAP + p1] = t;
        g_tok_e[2*t] = e0; g_tok_e[2*t+1] = e1;
        g_tok_p[2*t] = p0; g_tok_p[2*t+1] = p1;
        g_tok_w[2*t] = w0; g_tok_w[2*t+1] = w1;
    }
}

// ---------------- 2) GEMM1 (fp16 mma, 512 thr): h = silu(X W1)*(X W2) ------
__global__ __launch_bounds__(512, 1) void gemm1_tc() {
    int g = blockIdx.z;
    int n = (g == 8) ? TOK : g_counts[g];
    int row0 = blockIdx.x * MT;
    if (row0 >= n) return;
    int col0 = blockIdx.y * NT;
    const __half* B1g = g_w1h + (size_t)g * DIM * HID;
    const __half* B2g = g_w2h + (size_t)g * DIM * HID;

    extern __shared__ char dynb[];
    __shared__ int toks[MT];
    int tid = threadIdx.x, lane = tid & 31, wid = tid >> 5;

    if (tid < MT) {
        int r = row0 + tid;
        toks[tid] = (r < n) ? ((g == 8) ? r : g_rows[g * CAP + r]) : -1;
    }
    __syncthreads();

    uint32_t sbase = smem_u32(dynb);
    // producers: A = 128 rows x 32 halves (4 x 16B chunks/row)
    int am = tid >> 2, aq = tid & 3;
    int atok = toks[am];
    const __half* asrc = g_xh + ((atok >= 0) ? (size_t)atok * DIM : 0) + aq * 8;
    int asz = (atok >= 0) ? 16 : 0;
    uint32_t adst = sbase + am * (AS * 2) + aq * 16;
    // B: 32 k-rows x 128 cols x 2 mats; 16 chunks of 16B per row per mat
    int brow = tid >> 4, bch = tid & 15;
    const __half* b1src = B1g + (size_t)brow * HID + col0 + bch * 8;
    const __half* b2src = B2g + (size_t)brow * HID + col0 + bch * 8;
    uint32_t bdst = sbase + A_BYTES + brow * (BSH * 2) + bch * 16;

    const int NC = DIM / KT;  // 32

    auto prefetch = [&](int c) {
        uint32_t so = (uint32_t)(c % 3) * STG1;
        cpa16z(adst + so, asrc + c * 32, asz);
        cpa16(bdst + so,           b1src + (size_t)(c * 32) * HID);
        cpa16(bdst + so + B_BYTES, b2src + (size_t)(c * 32) * HID);
    };

    prefetch(0); CP_COMMIT();
    prefetch(1); CP_COMMIT();

    float acc1[2][4][4] = {};
    float acc2[2][4][4] = {};
    int wm = (wid & 3) * 32, wn = (wid >> 2) * 32;   // warp tile 32x32
    uint32_t aoff = ((wm + (lane & 15)) * AS + (lane >> 4) * 8) * 2;
    uint32_t boff = ((lane & 15) * BSH + wn + (lane >> 4) * 8) * 2;

    for (int c = 0; c < NC; c++) {
        CP_WAIT(1);
        __syncthreads();
        if (c + 2 < NC) prefetch(c + 2);
        CP_COMMIT();
        uint32_t As_u = sbase + (uint32_t)(c % 3) * STG1;
        uint32_t B1_u = As_u + A_BYTES;
        uint32_t B2_u = B1_u + B_BYTES;
        #pragma unroll
        for (int kk = 0; kk < 2; kk++) {
            uint32_t af[2][4];
            #pragma unroll
            for (int mf = 0; mf < 2; mf++)
                ldsm4(af[mf], As_u + aoff + mf * (16 * AS * 2) + kk * 32);
            #pragma unroll
            for (int nfp = 0; nfp < 2; nfp++) {
                uint32_t bb = boff + nfp * 32 + kk * (16 * BSH * 2);
                uint32_t b1[4], b2[4];
                ldsm4t(b1, B1_u + bb);
                ldsm4t(b2, B2_u + bb);
                #pragma unroll
                for (int mf = 0; mf < 2; mf++) {
                    mma16(acc1[mf][nfp * 2],     af[mf], b1);
                    mma16(acc1[mf][nfp * 2 + 1], af[mf], b1 + 2);
                    mma16(acc2[mf][nfp * 2],     af[mf], b2);
                    mma16(acc2[mf][nfp * 2 + 1], af[mf], b2 + 2);
                }
            }
        }
    }

    // epilogue: silu(acc1)*acc2 -> g_hh (fp16)
    #pragma unroll
    for (int mf = 0; mf < 2; mf++) {
        #pragma unroll
        for (int h = 0; h < 2; h++) {
            int r = row0 + wm + mf * 16 + (lane >> 2) + h * 8;
            if (r < n) {
                __half* hp = g_hh + ((size_t)g * CAP + r) * HID + col0 + wn + (lane & 3) * 2;
                #pragma unroll
                for (int nf = 0; nf < 4; nf++) {
                    float a0 = acc1[mf][nf][h * 2], a1 = acc1[mf][nf][h * 2 + 1];
                    float s0 = a0 / (1.f + __expf(-a0));
                    float s1 = a1 / (1.f + __expf(-a1));
                    *(__half2*)(hp + nf * 8) =
                        __floats2half2_rn(s0 * acc2[mf][nf][h * 2],
                                          s1 * acc2[mf][nf][h * 2 + 1]);
                }
            }
        }
    }
}

// ---------------- 3) GEMM2 (fp16 mma, 2 CTA/SM): y = h W3 ------------------
__global__ __launch_bounds__(256, 2) void gemm2_tc() {
    int g = blockIdx.z;
    int n = (g == 8) ? TOK : g_counts[g];
    int row0 = blockIdx.x * MT;
    if (row0 >= n) return;
    int col0 = blockIdx.y * NT;
    const __half* Bg = g_w3h + (size_t)g * HID * DIM;

    extern __shared__ char dynb[];
    int tid = threadIdx.x, lane = tid & 31, wid = tid >> 5;
    uint32_t sbase = smem_u32(dynb);

    int am = tid >> 1, aq = (tid & 1) * 2;
    int ar = row0 + am;
    const __half* asrc = g_hh + ((ar < n) ? ((size_t)g * CAP + ar) * HID : 0) + aq * 8;
    int asz = (ar < n) ? 16 : 0;
    uint32_t adst = sbase + am * (AS * 2) + aq * 16;
    int brow = tid >> 3, bch = (tid & 7) * 2;
    const __half* bsrc = Bg + (size_t)brow * DIM + col0 + bch * 8;
    uint32_t bdst = sbase + A_BYTES + brow * (BSH * 2) + bch * 16;

    const int NC = HID / KT;  // 128

    auto prefetch = [&](int c) {
        uint32_t so = (uint32_t)(c & 3) * STG2;
        cpa16z(adst + so,      asrc + c * 32,     asz);
        cpa16z(adst + so + 16, asrc + c * 32 + 8, asz);
        const __half* p = bsrc + (size_t)(c * 32) * DIM;
        cpa16(bdst + so,      p);
        cpa16(bdst + so + 16, p + 8);
    };

    prefetch(0); CP_COMMIT();
    prefetch(1); CP_COMMIT();
    prefetch(2); CP_COMMIT();

    float acc[4][4][4] = {};
    int wm = (wid & 1) * 64, wn = (wid >> 1) * 32;
    uint32_t aoff = ((wm + (lane & 15)) * AS + (lane >> 4) * 8) * 2;
    uint32_t boff = ((lane & 15) * BSH + wn + (lane >> 4) * 8) * 2;

    for (int c = 0; c < NC; c++) {
        CP_WAIT(2);
        __syncthreads();
        if (c + 3 < NC) prefetch(c + 3);
        CP_COMMIT();
        uint32_t As_u = sbase + (uint32_t)(c & 3) * STG2;
        uint32_t B_u  = As_u + A_BYTES;
        #pragma unroll
        for (int kk = 0; kk < 2; kk++) {
            uint32_t af[4][4];
            #pragma unroll
            for (int mf = 0; mf < 4; mf++)
                ldsm4(af[mf], As_u + aoff + mf * (16 * AS * 2) + kk * 32);
            #pragma unroll
            for (int nfp = 0; nfp < 2; nfp++) {
                uint32_t bb = boff + nfp * 32 + kk * (16 * BSH * 2);
                uint32_t b[4];
                ldsm4t(b, B_u + bb);
                #pragma unroll
                for (int mf = 0; mf < 4; mf++) {
                    mma16(acc[mf][nfp * 2],     af[mf], b);
                    mma16(acc[mf][nfp * 2 + 1], af[mf], b + 2);
                }
            }
        }
    }

    #pragma unroll
    for (int mf = 0; mf < 4; mf++) {
        #pragma unroll
        for (int h = 0; h < 2; h++) {
            int r = row0 + wm + mf * 16 + (lane >> 2) + h * 8;
            if (r < n) {
                float* yp = g_y + ((size_t)g * CAP + r) * DIM + col0 + wn + (lane & 3) * 2;
                #pragma unroll
                for (int nf = 0; nf < 4; nf++)
                    *(float2*)(yp + nf * 8) =
                        make_float2(acc[mf][nf][h * 2], acc[mf][nf][h * 2 + 1]);
            }
        }
    }
}

// ---------------- 4) combine ----------------
__global__ __launch_bounds__(256) void combine_k(float* __restrict__ out) {
    int t = blockIdx.x;
    int tid = threadIdx.x;
    int e0 = g_tok_e[2*t], e1 = g_tok_e[2*t+1];
    int p0 = g_tok_p[2*t], p1 = g_tok_p[2*t+1];
    float w0 = g_tok_w[2*t], w1 = g_tok_w[2*t+1];
    const float4* ys = (const float4*)(g_y + ((size_t)8 * CAP + t) * DIM);
    const float4* y0 = (const float4*)(g_y + ((size_t)e0 * CAP + p0) * DIM);
    const float4* y1 = (const float4*)(g_y + ((size_t)e1 * CAP + p1) * DIM);
    float4* op = (float4*)(out + (size_t)t * DIM);
    float4 a = ys[tid], b = y0[tid], c = y1[tid];
    float4 o;
    o.x = a.x + w0 * b.x + w1 * c.x;
    o.y = a.y + w0 * b.y + w1 * c.y;
    o.z = a.z + w0 * b.z + w1 * c.z;
    o.w = a.w + w0 * b.w + w1 * c.w;
    op[tid] = o;
}

// ---------------- launch ----------------
extern "C" void kernel_launch(void* const* d_in, const int* in_sizes, int n_in,
                              void* d_out, int out_size) {
    const float* x   = (const float*)d_in[0];
    const float* sw1 = (const float*)d_in[1];
    const float* sw2 = (const float*)d_in[2];
    const float* sw3 = (const float*)d_in[3];
    const float* w1  = (const float*)d_in[4];
    const float* w2  = (const float*)d_in[5];
    const float* w3  = (const float*)d_in[6];
    const float* rw  = (const float*)d_in[7];
    float* out    = (float*)d_out;
    float* logits = out + (size_t)TOK * DIM;

    cudaFuncSetAttribute(gemm1_tc, cudaFuncAttributeMaxDynamicSharedMemorySize, SMEM1);
    cudaFuncSetAttribute(gemm2_tc, cudaFuncAttributeMaxDynamicSharedMemorySize, SMEM2);

    void* cptr = nullptr;
    cudaGetSymbolAddress(&cptr, g_counts);
    cudaMemsetAsync(cptr, 0, NE * sizeof(int));

    convert_k<<<dim3(864, 7), 256>>>(x, sw1, sw2, sw3, w1, w2, w3);
    router_k<<<TOK, 256>>>(x, rw, logits);
    gemm1_tc<<<dim3(CAP / MT, HID / NT, NG), 512, SMEM1>>>();
    gemm2_tc<<<dim3(CAP / MT, DIM / NT, NG), 256, SMEM2>>>();
    combine_k<<<TOK, 256>>>(out);
}